// round 4
// baseline (speedup 1.0000x reference)
#include <cuda_runtime.h>
#include <cuda_bf16.h>
#include <stdint.h>

#define IN_F   4096
#define OUT_F  4096
#define M_TOT  8192
#define NGRP   32

// ---------------- scratch (static device globals; no dynamic alloc) ------
__device__ __nv_bfloat16 g_xh[(size_t)M_TOT * IN_F];   // 64 MiB: bf16 hi of permuted x
__device__ __nv_bfloat16 g_xl[(size_t)M_TOT * IN_F];   // 64 MiB: bf16 lo residual
__device__ __nv_bfloat16 g_wq[(size_t)OUT_F * IN_F];   // 32 MiB: exact int4 values in bf16

// ---------------- PTX helpers (base sm_80/90 PTX only — no tcgen05) ------
__device__ __forceinline__ uint32_t smem_u32(const void* p) {
    uint32_t a;
    asm("{ .reg .u64 t; cvta.to.shared.u64 t, %1; cvt.u32.u64 %0, t; }"
        : "=r"(a) : "l"(p));
    return a;
}
__device__ __forceinline__ void cp16(uint32_t dst, const void* src) {
    asm volatile("cp.async.cg.shared.global [%0], [%1], 16;" :: "r"(dst), "l"(src) : "memory");
}
__device__ __forceinline__ void cp_commit() {
    asm volatile("cp.async.commit_group;" ::: "memory");
}
__device__ __forceinline__ void cp_wait1() {
    asm volatile("cp.async.wait_group 1;" ::: "memory");
}
__device__ __forceinline__ void ldm_x4(uint32_t* r, uint32_t addr) {
    asm volatile("ldmatrix.sync.aligned.m8n8.x4.shared.b16 {%0,%1,%2,%3}, [%4];"
                 : "=r"(r[0]), "=r"(r[1]), "=r"(r[2]), "=r"(r[3]) : "r"(addr));
}
__device__ __forceinline__ void mma16816(float* d, const uint32_t* a, const uint32_t* b) {
    asm volatile(
        "mma.sync.aligned.m16n8k16.row.col.f32.bf16.bf16.f32 "
        "{%0,%1,%2,%3}, {%4,%5,%6,%7}, {%8,%9}, {%0,%1,%2,%3};"
        : "+f"(d[0]), "+f"(d[1]), "+f"(d[2]), "+f"(d[3])
        : "r"(a[0]), "r"(a[1]), "r"(a[2]), "r"(a[3]), "r"(b[0]), "r"(b[1]));
}

// ---------------- prep kernels ------------------------------------------
// xh/xl = bf16 hi/lo split of permuted activations (row staged in SMEM so the
// gather is cheap; all gmem traffic coalesced)
__global__ void prep_x_kernel(const float* __restrict__ x, const int* __restrict__ perm) {
    __shared__ float row[IN_F];
    const int m = blockIdx.x;
    const float* xr = x + (size_t)m * IN_F;
    for (int j = threadIdx.x; j < IN_F; j += blockDim.x) row[j] = xr[j];
    __syncthreads();
    for (int k = threadIdx.x; k < IN_F; k += blockDim.x) {
        float v = row[perm[k]];
        __nv_bfloat16 h = __float2bfloat16(v);
        __nv_bfloat16 l = __float2bfloat16(v - __bfloat162float(h));
        g_xh[(size_t)m * IN_F + k] = h;
        g_xl[(size_t)m * IN_F + k] = l;
    }
}

// wq = unpacked int4 values, EXACT in bf16 (integers in [-8,7]); the group
// scale is applied in the GEMM epilogue per K=128 group, so no precision loss.
__global__ void prep_w_kernel(const int* __restrict__ wp) {
    const int idx = blockIdx.x * blockDim.x + threadIdx.x;   // over OUT_F * IN_F/2
    const int b = wp[idx];
    __nv_bfloat16 q0 = __float2bfloat16((float)((b & 0xF) - 8));
    __nv_bfloat16 q1 = __float2bfloat16((float)(((b >> 4) & 0xF) - 8));
    *reinterpret_cast<__nv_bfloat162*>(&g_wq[(size_t)idx * 2]) = __halves2bfloat162(q0, q1);
}

// ---------------- GEMM --------------------------------------------------
// CTA tile 128x128, BK=128 (= one scale group), 256 threads, 8 warps (4m x 2n),
// warp tile 32x64. 3-stage cp.async pipeline. Two K passes (xh then xl) into
// one accumulator; per-group scale merged from a temp accumulator.
#define BM 128
#define BN 128
#define BK 128
#define NST 3
#define NIT 64                    // 2 passes * 32 groups
#define STG 65536                 // 64 KiB per stage: A 32K + B 32K
#define SCL_OFF (NST * STG)       // 196608
#define SMEM_BYTES (SCL_OFF + NGRP * BN * 4)   // + 16 KiB scales = 212992

// Stage layout: A at +0, B at +32768. Each is two K-half sub-tiles of
// [128 rows x 64 bf16] with 128-byte rows, SW128-style swizzle:
// phys_chunk = chunk ^ (row & 7), chunk = 16B unit.
__device__ __forceinline__ void load_stage(int it, int tid, int m0, int n0, uint32_t sb) {
    const __nv_bfloat16* A = (it < 32) ? g_xh : g_xl;
    const size_t k0 = (size_t)(it & 31) * BK;
    const uint32_t st = sb + (uint32_t)(it % NST) * STG;
#pragma unroll
    for (int u = 0; u < 8; ++u) {
        const int q = tid + u * 256;                   // 0..2047
        const int row = q >> 4, h = (q >> 3) & 1, c = q & 7;
        const uint32_t so = st + h * 16384 + row * 128 + ((c ^ (row & 7)) << 4);
        cp16(so, A + (size_t)(m0 + row) * IN_F + k0 + h * 64 + c * 8);
    }
#pragma unroll
    for (int u = 0; u < 8; ++u) {
        const int q = tid + u * 256;
        const int row = q >> 4, h = (q >> 3) & 1, c = q & 7;
        const uint32_t so = st + 32768 + h * 16384 + row * 128 + ((c ^ (row & 7)) << 4);
        cp16(so, g_wq + (size_t)(n0 + row) * IN_F + k0 + h * 64 + c * 8);
    }
}

__global__ __launch_bounds__(256, 1)
void gptq_gemm_kernel(float* __restrict__ out, const float* __restrict__ ws,
                      const float* __restrict__ bias) {
    extern __shared__ char smem[];
    const uint32_t sb = smem_u32(smem);
    const int tid = threadIdx.x;
    const int wid = tid >> 5, l = tid & 31;
    const int wm = wid & 3, wn = wid >> 2;             // 4 m-warps x 2 n-warps
    const int l7 = l & 7, mtx = l >> 3;
    const int arow = ((mtx & 1) << 3) + l7;            // A ldmatrix row offset
    const int amch = mtx >> 1;                         // A ldmatrix chunk offset
    const int brow = ((mtx >> 1) << 3) + l7;           // B ldmatrix row offset
    const int bmch = mtx & 1;                          // B ldmatrix chunk offset

    const int m0 = (int)(blockIdx.x >> 5) * BM;        // 64 m-tiles
    const int n0 = (int)(blockIdx.x & 31) * BN;        // 32 n-tiles

    // stage this CTA's n-block scales: sScale[g*128 + nl] = ws[(n0+nl)*32 + g]
    float* sScale = reinterpret_cast<float*>(smem + SCL_OFF);
    for (int i = tid; i < NGRP * BN; i += 256) {
        const int g = i >> 7, nl = i & 127;
        sScale[i] = ws[(size_t)(n0 + nl) * NGRP + g];
    }

    float yacc[2][8][4];
    float tacc[2][8][4];
#pragma unroll
    for (int mi = 0; mi < 2; ++mi)
#pragma unroll
        for (int nj = 0; nj < 8; ++nj)
#pragma unroll
            for (int e = 0; e < 4; ++e) { yacc[mi][nj][e] = 0.f; tacc[mi][nj][e] = 0.f; }

    load_stage(0, tid, m0, n0, sb); cp_commit();
    load_stage(1, tid, m0, n0, sb); cp_commit();

    const float* scBase = sScale + wn * 64 + (l & 3) * 2;

#pragma unroll 1
    for (int it = 0; it < NIT; ++it) {
        cp_wait1();                 // stage it resident
        __syncthreads();            // all warps done with buffer (it+2)%3
        if (it + 2 < NIT) load_stage(it + 2, tid, m0, n0, sb);
        cp_commit();

        const uint32_t stA = sb + (uint32_t)(it % NST) * STG;
        const uint32_t stB = stA + 32768;

#pragma unroll
        for (int ks = 0; ks < 8; ++ks) {
            const int h = ks >> 2;
            const int kc = (ks & 3) * 2;               // chunk base within half
            uint32_t a[2][4];
#pragma unroll
            for (int mi = 0; mi < 2; ++mi) {
                const int row = wm * 32 + mi * 16 + arow;
                const int c = (kc + amch) ^ l7;
                ldm_x4(a[mi], stA + h * 16384 + row * 128 + (c << 4));
            }
            uint32_t b[8][2];
#pragma unroll
            for (int bj = 0; bj < 4; ++bj) {
                const int n = wn * 64 + bj * 16 + brow;
                const int c = (kc + bmch) ^ l7;
                ldm_x4(&b[2 * bj][0], stB + h * 16384 + n * 128 + (c << 4));
            }
#pragma unroll
            for (int mi = 0; mi < 2; ++mi)
#pragma unroll
                for (int nj = 0; nj < 8; ++nj)
                    mma16816(tacc[mi][nj], a[mi], b[nj]);
        }

        // scale-merge this group: y += s[n,g] * temp; temp = 0
        const int g = it & 31;
        const float* sc = scBase + g * 128;
#pragma unroll
        for (int nj = 0; nj < 8; ++nj) {
            const float2 s = *reinterpret_cast<const float2*>(sc + nj * 8);
#pragma unroll
            for (int mi = 0; mi < 2; ++mi) {
                yacc[mi][nj][0] = fmaf(s.x, tacc[mi][nj][0], yacc[mi][nj][0]);
                yacc[mi][nj][1] = fmaf(s.y, tacc[mi][nj][1], yacc[mi][nj][1]);
                yacc[mi][nj][2] = fmaf(s.x, tacc[mi][nj][2], yacc[mi][nj][2]);
                yacc[mi][nj][3] = fmaf(s.y, tacc[mi][nj][3], yacc[mi][nj][3]);
                tacc[mi][nj][0] = 0.f; tacc[mi][nj][1] = 0.f;
                tacc[mi][nj][2] = 0.f; tacc[mi][nj][3] = 0.f;
            }
        }
    }

    // epilogue: + bias, fp32 out
#pragma unroll
    for (int mi = 0; mi < 2; ++mi) {
        const int r0 = m0 + wm * 32 + mi * 16 + (l >> 2);
#pragma unroll
        for (int nj = 0; nj < 8; ++nj) {
            const int c = n0 + wn * 64 + nj * 8 + (l & 3) * 2;
            const float2 bb = *reinterpret_cast<const float2*>(bias + c);
            float2 o0, o1;
            o0.x = yacc[mi][nj][0] + bb.x;  o0.y = yacc[mi][nj][1] + bb.y;
            o1.x = yacc[mi][nj][2] + bb.x;  o1.y = yacc[mi][nj][3] + bb.y;
            *reinterpret_cast<float2*>(out + (size_t)r0 * OUT_F + c) = o0;
            *reinterpret_cast<float2*>(out + (size_t)(r0 + 8) * OUT_F + c) = o1;
        }
    }
}

// ---------------- launch -------------------------------------------------
extern "C" void kernel_launch(void* const* d_in, const int* in_sizes, int n_in,
                              void* d_out, int out_size) {
    (void)in_sizes; (void)n_in; (void)out_size;
    const float* x    = (const float*)d_in[0];
    const int*   wp   = (const int*)  d_in[1];
    const float* ws   = (const float*)d_in[2];
    const int*   perm = (const int*)  d_in[3];
    const float* bias = (const float*)d_in[4];
    float* out = (float*)d_out;

    cudaFuncSetAttribute(gptq_gemm_kernel,
                         cudaFuncAttributeMaxDynamicSharedMemorySize, SMEM_BYTES);

    prep_x_kernel<<<M_TOT, 256>>>(x, perm);
    prep_w_kernel<<<(OUT_F * (IN_F / 2)) / 256, 256>>>(wp);
    gptq_gemm_kernel<<<(M_TOT / BM) * (OUT_F / BN), 256, SMEM_BYTES>>>(out, ws, bias);
}

// round 6
// speedup vs baseline: 2.0250x; 2.0250x over previous
#include <cuda_runtime.h>
#include <cuda_fp16.h>
#include <stdint.h>

#define IN_F   4096
#define OUT_F  4096
#define M_TOT  8192
#define NGRP   32

// ---------------- scratch (static device globals; no dynamic alloc) ------
__device__ __half g_xf[(size_t)M_TOT * IN_F];   // 64 MiB: fp16 permuted x
__device__ __half g_wf[(size_t)OUT_F * IN_F];   // 32 MiB: fp16 dequantized w (q*s)

// ---------------- PTX helpers (base PTX only — no tcgen05 on this toolchain)
__device__ __forceinline__ uint32_t smem_u32(const void* p) {
    uint32_t a;
    asm("{ .reg .u64 t; cvta.to.shared.u64 t, %1; cvt.u32.u64 %0, t; }"
        : "=r"(a) : "l"(p));
    return a;
}
__device__ __forceinline__ void cp16(uint32_t dst, const void* src) {
    asm volatile("cp.async.cg.shared.global [%0], [%1], 16;" :: "r"(dst), "l"(src) : "memory");
}
__device__ __forceinline__ void cp_commit() {
    asm volatile("cp.async.commit_group;" ::: "memory");
}
__device__ __forceinline__ void cp_wait1() {
    asm volatile("cp.async.wait_group 1;" ::: "memory");
}
__device__ __forceinline__ void ldm_x4(uint32_t* r, uint32_t addr) {
    asm volatile("ldmatrix.sync.aligned.m8n8.x4.shared.b16 {%0,%1,%2,%3}, [%4];"
                 : "=r"(r[0]), "=r"(r[1]), "=r"(r[2]), "=r"(r[3]) : "r"(addr));
}
__device__ __forceinline__ void mma16816(float* d, const uint32_t* a, const uint32_t* b) {
    asm volatile(
        "mma.sync.aligned.m16n8k16.row.col.f32.f16.f16.f32 "
        "{%0,%1,%2,%3}, {%4,%5,%6,%7}, {%8,%9}, {%0,%1,%2,%3};"
        : "+f"(d[0]), "+f"(d[1]), "+f"(d[2]), "+f"(d[3])
        : "r"(a[0]), "r"(a[1]), "r"(a[2]), "r"(a[3]), "r"(b[0]), "r"(b[1]));
}

// ---------------- prep kernels ------------------------------------------
// fp16 permuted activations (row staged in SMEM so the gather is cheap)
__global__ void prep_x_kernel(const float* __restrict__ x, const int* __restrict__ perm) {
    __shared__ float row[IN_F];
    const int m = blockIdx.x;
    const float* xr = x + (size_t)m * IN_F;
    for (int j = threadIdx.x; j < IN_F; j += blockDim.x) row[j] = xr[j];
    __syncthreads();
    for (int k = threadIdx.x; k < IN_F; k += blockDim.x)
        g_xf[(size_t)m * IN_F + k] = __float2half(row[perm[k]]);
}

// w = (q - 8) * group_scale, stored fp16 (|w| <= 0.16, always normal-range)
__global__ void prep_w_kernel(const int* __restrict__ wp, const float* __restrict__ ws) {
    const int idx = blockIdx.x * blockDim.x + threadIdx.x;   // over OUT_F * IN_F/2
    const int n  = idx >> 11;
    const int kk = idx & 2047;
    const int b  = wp[idx];
    const float s = ws[n * NGRP + (kk >> 6)];
    __half h0 = __float2half((float)((b & 0xF) - 8) * s);
    __half h1 = __float2half((float)(((b >> 4) & 0xF) - 8) * s);
    *reinterpret_cast<__half2*>(&g_wf[(size_t)idx * 2]) = __halves2half2(h0, h1);
}

// ---------------- GEMM --------------------------------------------------
// CTA tile 128x128, BK=128, 256 threads, 8 warps (4m x 2n), warp tile 32x64.
// 3-stage cp.async pipeline; single fp16 pass, fp32 accumulate, bias epilogue.
#define BM 128
#define BN 128
#define BK 128
#define NST 3
#define NIT 32                    // 4096 / BK
#define STG 65536                 // 64 KiB per stage: A 32K + B 32K
#define SMEM_BYTES (NST * STG)    // 196608

// Stage layout: A at +0, B at +32768. Each half-K sub-tile is [128 rows x 64 fp16]
// with 128-byte rows; swizzle: phys_chunk = chunk ^ (row & 7), chunk = 16B unit.
__device__ __forceinline__ void load_stage(int it, int tid, int m0, int n0, uint32_t sb) {
    const size_t k0 = (size_t)it * BK;
    const uint32_t st = sb + (uint32_t)(it % NST) * STG;
#pragma unroll
    for (int u = 0; u < 8; ++u) {
        const int q = tid + u * 256;                   // 0..2047
        const int row = q >> 4, h = (q >> 3) & 1, c = q & 7;
        const uint32_t so = st + h * 16384 + row * 128 + ((c ^ (row & 7)) << 4);
        cp16(so, g_xf + (size_t)(m0 + row) * IN_F + k0 + h * 64 + c * 8);
    }
#pragma unroll
    for (int u = 0; u < 8; ++u) {
        const int q = tid + u * 256;
        const int row = q >> 4, h = (q >> 3) & 1, c = q & 7;
        const uint32_t so = st + 32768 + h * 16384 + row * 128 + ((c ^ (row & 7)) << 4);
        cp16(so, g_wf + (size_t)(n0 + row) * IN_F + k0 + h * 64 + c * 8);
    }
}

__global__ __launch_bounds__(256, 1)
void gptq_gemm_kernel(float* __restrict__ out, const float* __restrict__ bias) {
    extern __shared__ char smem[];
    const uint32_t sb = smem_u32(smem);
    const int tid = threadIdx.x;
    const int wid = tid >> 5, l = tid & 31;
    const int wm = wid & 3, wn = wid >> 2;             // 4 m-warps x 2 n-warps
    const int l7 = l & 7, mtx = l >> 3;
    const int arow = ((mtx & 1) << 3) + l7;            // A ldmatrix row offset
    const int amch = mtx >> 1;                         // A ldmatrix chunk offset
    const int brow = ((mtx >> 1) << 3) + l7;           // B ldmatrix row offset
    const int bmch = mtx & 1;                          // B ldmatrix chunk offset

    const int m0 = (int)(blockIdx.x >> 5) * BM;        // 64 m-tiles
    const int n0 = (int)(blockIdx.x & 31) * BN;        // 32 n-tiles

    float yacc[2][8][4];
#pragma unroll
    for (int mi = 0; mi < 2; ++mi)
#pragma unroll
        for (int nj = 0; nj < 8; ++nj)
#pragma unroll
            for (int e = 0; e < 4; ++e) yacc[mi][nj][e] = 0.f;

    load_stage(0, tid, m0, n0, sb); cp_commit();
    load_stage(1, tid, m0, n0, sb); cp_commit();

#pragma unroll 1
    for (int it = 0; it < NIT; ++it) {
        cp_wait1();                 // stage it resident
        __syncthreads();            // all warps done with buffer (it+2)%3
        if (it + 2 < NIT) load_stage(it + 2, tid, m0, n0, sb);
        cp_commit();                // empty group in tail keeps wait count uniform

        const uint32_t stA = sb + (uint32_t)(it % NST) * STG;
        const uint32_t stB = stA + 32768;

#pragma unroll
        for (int ks = 0; ks < 8; ++ks) {
            const int h = ks >> 2;
            const int kc = (ks & 3) * 2;               // 16B-chunk base within half
            uint32_t a[2][4];
#pragma unroll
            for (int mi = 0; mi < 2; ++mi) {
                const int row = wm * 32 + mi * 16 + arow;
                const int c = (kc + amch) ^ l7;
                ldm_x4(a[mi], stA + h * 16384 + row * 128 + (c << 4));
            }
            uint32_t b[8][2];
#pragma unroll
            for (int bj = 0; bj < 4; ++bj) {
                const int n = wn * 64 + bj * 16 + brow;
                const int c = (kc + bmch) ^ l7;
                ldm_x4(&b[2 * bj][0], stB + h * 16384 + n * 128 + (c << 4));
            }
#pragma unroll
            for (int mi = 0; mi < 2; ++mi)
#pragma unroll
                for (int nj = 0; nj < 8; ++nj)
                    mma16816(yacc[mi][nj], a[mi], b[nj]);
        }
    }

    // epilogue: + bias, fp32 out
#pragma unroll
    for (int mi = 0; mi < 2; ++mi) {
        const int r0 = m0 + wm * 32 + mi * 16 + (l >> 2);
#pragma unroll
        for (int nj = 0; nj < 8; ++nj) {
            const int c = n0 + wn * 64 + nj * 8 + (l & 3) * 2;
            const float2 bb = *reinterpret_cast<const float2*>(bias + c);
            float2 o0, o1;
            o0.x = yacc[mi][nj][0] + bb.x;  o0.y = yacc[mi][nj][1] + bb.y;
            o1.x = yacc[mi][nj][2] + bb.x;  o1.y = yacc[mi][nj][3] + bb.y;
            *reinterpret_cast<float2*>(out + (size_t)r0 * OUT_F + c) = o0;
            *reinterpret_cast<float2*>(out + (size_t)(r0 + 8) * OUT_F + c) = o1;
        }
    }
}

// ---------------- launch -------------------------------------------------
extern "C" void kernel_launch(void* const* d_in, const int* in_sizes, int n_in,
                              void* d_out, int out_size) {
    (void)in_sizes; (void)n_in; (void)out_size;
    const float* x    = (const float*)d_in[0];
    const int*   wp   = (const int*)  d_in[1];
    const float* ws   = (const float*)d_in[2];
    const int*   perm = (const int*)  d_in[3];
    const float* bias = (const float*)d_in[4];
    float* out = (float*)d_out;

    cudaFuncSetAttribute(gptq_gemm_kernel,
                         cudaFuncAttributeMaxDynamicSharedMemorySize, SMEM_BYTES);

    prep_x_kernel<<<M_TOT, 256>>>(x, perm);
    prep_w_kernel<<<(OUT_F * (IN_F / 2)) / 256, 256>>>(wp, ws);
    gptq_gemm_kernel<<<(M_TOT / BM) * (OUT_F / BN), 256, SMEM_BYTES>>>(out, bias);
}

// round 10
// speedup vs baseline: 2.1573x; 1.0653x over previous
#include <cuda_runtime.h>
#include <cuda_fp16.h>
#include <stdint.h>

#define IN_F   4096
#define OUT_F  4096
#define M_TOT  8192
#define NGRP   32

// ---------------- scratch (static device globals; no dynamic alloc) ------
__device__ __half g_xf[(size_t)M_TOT * IN_F];   // 64 MiB: fp16 permuted x
__device__ __half g_wf[(size_t)OUT_F * IN_F];   // 32 MiB: fp16 dequantized w (q*s)

// ---------------- PTX helpers (base PTX only — no tcgen05 on this toolchain)
__device__ __forceinline__ uint32_t smem_u32(const void* p) {
    uint32_t a;
    asm("{ .reg .u64 t; cvta.to.shared.u64 t, %1; cvt.u32.u64 %0, t; }"
        : "=r"(a) : "l"(p));
    return a;
}
__device__ __forceinline__ void cp16(uint32_t dst, const void* src) {
    asm volatile("cp.async.cg.shared.global [%0], [%1], 16;" :: "r"(dst), "l"(src) : "memory");
}
__device__ __forceinline__ void cp_commit() {
    asm volatile("cp.async.commit_group;" ::: "memory");
}
__device__ __forceinline__ void cp_wait2() {
    asm volatile("cp.async.wait_group 2;" ::: "memory");
}
__device__ __forceinline__ void ldm_x4(uint32_t* r, uint32_t addr) {
    asm volatile("ldmatrix.sync.aligned.m8n8.x4.shared.b16 {%0,%1,%2,%3}, [%4];"
                 : "=r"(r[0]), "=r"(r[1]), "=r"(r[2]), "=r"(r[3]) : "r"(addr));
}
__device__ __forceinline__ void mma16816(float* d, const uint32_t* a, const uint32_t* b) {
    asm volatile(
        "mma.sync.aligned.m16n8k16.row.col.f32.f16.f16.f32 "
        "{%0,%1,%2,%3}, {%4,%5,%6,%7}, {%8,%9}, {%0,%1,%2,%3};"
        : "+f"(d[0]), "+f"(d[1]), "+f"(d[2]), "+f"(d[3])
        : "r"(a[0]), "r"(a[1]), "r"(a[2]), "r"(a[3]), "r"(b[0]), "r"(b[1]));
}

// ---------------- prep kernels ------------------------------------------
// fp16 permuted activations (row staged in SMEM so the gather is cheap)
__global__ void prep_x_kernel(const float* __restrict__ x, const int* __restrict__ perm) {
    __shared__ float row[IN_F];
    const int m = blockIdx.x;
    const float* xr = x + (size_t)m * IN_F;
    for (int j = threadIdx.x; j < IN_F; j += blockDim.x) row[j] = xr[j];
    __syncthreads();
    for (int k = threadIdx.x; k < IN_F; k += blockDim.x)
        g_xf[(size_t)m * IN_F + k] = __float2half(row[perm[k]]);
}

// w = (q - 8) * group_scale, stored fp16 (|w| <= 0.16, always normal-range)
__global__ void prep_w_kernel(const int* __restrict__ wp, const float* __restrict__ ws) {
    const int idx = blockIdx.x * blockDim.x + threadIdx.x;   // over OUT_F * IN_F/2
    const int n  = idx >> 11;
    const int kk = idx & 2047;
    const int b  = wp[idx];
    const float s = ws[n * NGRP + (kk >> 6)];
    __half h0 = __float2half((float)((b & 0xF) - 8) * s);
    __half h1 = __float2half((float)(((b >> 4) & 0xF) - 8) * s);
    *reinterpret_cast<__half2*>(&g_wf[(size_t)idx * 2]) = __halves2half2(h0, h1);
}

// ---------------- GEMM --------------------------------------------------
// CTA tile 256x128, BK=64, 256 threads, 8 warps (4m x 2n), warp tile 64x64.
// 4-stage cp.async pipeline; single fp16 pass, fp32 accumulate, bias epilogue.
#define BM 256
#define BN 128
#define BK 64
#define NST 4
#define NIT 64                    // 4096 / BK
#define STG_A (BM * 128)          // 32 KiB (256 rows x 128B)
#define STG_B (BN * 128)          // 16 KiB (128 rows x 128B)
#define STG (STG_A + STG_B)       // 48 KiB per stage
#define SMEM_BYTES (NST * STG)    // 196608

// Rows are 64 fp16 = 128 bytes; swizzle: phys 16B-chunk = chunk ^ (row & 7).
__device__ __forceinline__ void load_stage(int it, int tid, int m0, int n0, uint32_t sb) {
    const size_t k0 = (size_t)it * BK;
    const uint32_t st = sb + (uint32_t)(it % NST) * STG;
#pragma unroll
    for (int u = 0; u < 8; ++u) {                      // A: 2048 chunks
        const int q = tid + u * 256;
        const int row = q >> 3, c = q & 7;
        const uint32_t so = st + row * 128 + ((c ^ (row & 7)) << 4);
        cp16(so, g_xf + (size_t)(m0 + row) * IN_F + k0 + c * 8);
    }
#pragma unroll
    for (int u = 0; u < 4; ++u) {                      // B: 1024 chunks
        const int q = tid + u * 256;
        const int row = q >> 3, c = q & 7;
        const uint32_t so = st + STG_A + row * 128 + ((c ^ (row & 7)) << 4);
        cp16(so, g_wf + (size_t)(n0 + row) * IN_F + k0 + c * 8);
    }
}

__global__ __launch_bounds__(256, 1)
void gptq_gemm_kernel(float* __restrict__ out, const float* __restrict__ bias) {
    extern __shared__ char smem[];
    const uint32_t sb = smem_u32(smem);
    const int tid = threadIdx.x;
    const int wid = tid >> 5, l = tid & 31;
    const int wm = wid & 3, wn = wid >> 2;             // 4 m-warps x 2 n-warps
    const int l7 = l & 7, mtx = l >> 3;
    const int arow = ((mtx & 1) << 3) + l7;            // A ldmatrix row offset
    const int amch = mtx >> 1;                         // A ldmatrix chunk offset
    const int brow = ((mtx >> 1) << 3) + l7;           // B ldmatrix row offset
    const int bmch = mtx & 1;                          // B ldmatrix chunk offset

    const int m0 = (int)(blockIdx.x >> 5) * BM;        // 32 m-tiles
    const int n0 = (int)(blockIdx.x & 31) * BN;        // 32 n-tiles

    float yacc[4][8][4];
#pragma unroll
    for (int mi = 0; mi < 4; ++mi)
#pragma unroll
        for (int nj = 0; nj < 8; ++nj)
#pragma unroll
            for (int e = 0; e < 4; ++e) yacc[mi][nj][e] = 0.f;

    load_stage(0, tid, m0, n0, sb); cp_commit();
    load_stage(1, tid, m0, n0, sb); cp_commit();
    load_stage(2, tid, m0, n0, sb); cp_commit();

#pragma unroll 1
    for (int it = 0; it < NIT; ++it) {
        cp_wait2();                 // stage it resident (<= 2 groups pending)
        __syncthreads();            // all warps done computing stage it-1
        if (it + 3 < NIT) load_stage(it + 3, tid, m0, n0, sb);
        cp_commit();                // empty group in tail keeps wait count uniform

        const uint32_t stA = sb + (uint32_t)(it % NST) * STG;
        const uint32_t stB = stA + STG_A;

#pragma unroll
        for (int ks = 0; ks < 4; ++ks) {
            const int kc = ks * 2;                     // 16B-chunk base (k=16 per ks)
            uint32_t a[4][4];
#pragma unroll
            for (int mi = 0; mi < 4; ++mi) {
                const int row = wm * 64 + mi * 16 + arow;
                const int c = (kc + amch) ^ l7;
                ldm_x4(a[mi], stA + row * 128 + (c << 4));
            }
            uint32_t b[8][2];
#pragma unroll
            for (int bj = 0; bj < 4; ++bj) {
                const int n = wn * 64 + bj * 16 + brow;
                const int c = (kc + bmch) ^ l7;
                ldm_x4(&b[2 * bj][0], stB + n * 128 + (c << 4));
            }
#pragma unroll
            for (int mi = 0; mi < 4; ++mi)
#pragma unroll
                for (int nj = 0; nj < 8; ++nj)
                    mma16816(yacc[mi][nj], a[mi], b[nj]);
        }
    }

    // epilogue: + bias, fp32 out
#pragma unroll
    for (int mi = 0; mi < 4; ++mi) {
        const int r0 = m0 + wm * 64 + mi * 16 + (l >> 2);
#pragma unroll
        for (int nj = 0; nj < 8; ++nj) {
            const int c = n0 + wn * 64 + nj * 8 + (l & 3) * 2;
            const float2 bb = *reinterpret_cast<const float2*>(bias + c);
            float2 o0, o1;
            o0.x = yacc[mi][nj][0] + bb.x;  o0.y = yacc[mi][nj][1] + bb.y;
            o1.x = yacc[mi][nj][2] + bb.x;  o1.y = yacc[mi][nj][3] + bb.y;
            *reinterpret_cast<float2*>(out + (size_t)r0 * OUT_F + c) = o0;
            *reinterpret_cast<float2*>(out + (size_t)(r0 + 8) * OUT_F + c) = o1;
        }
    }
}

// ---------------- launch -------------------------------------------------
extern "C" void kernel_launch(void* const* d_in, const int* in_sizes, int n_in,
                              void* d_out, int out_size) {
    (void)in_sizes; (void)n_in; (void)out_size;
    const float* x    = (const float*)d_in[0];
    const int*   wp   = (const int*)  d_in[1];
    const float* ws   = (const float*)d_in[2];
    const int*   perm = (const int*)  d_in[3];
    const float* bias = (const float*)d_in[4];
    float* out = (float*)d_out;

    cudaFuncSetAttribute(gptq_gemm_kernel,
                         cudaFuncAttributeMaxDynamicSharedMemorySize, SMEM_BYTES);

    prep_x_kernel<<<M_TOT, 256>>>(x, perm);
    prep_w_kernel<<<(OUT_F * (IN_F / 2)) / 256, 256>>>(wp, ws);
    gptq_gemm_kernel<<<(M_TOT / BM) * (OUT_F / BN), 256, SMEM_BYTES>>>(out, bias);
}